// round 16
// baseline (speedup 1.0000x reference)
#include <cuda_runtime.h>

#define N     2048
#define FIN   512
#define F     64
#define NT    32            // 64-row tiles per dimension
#define NTRI  528           // NT*(NT+1)/2
#define KSPL  8             // k1 split-K factor

typedef unsigned long long u64;

// ---------------- scratch (static device allocations only) ----------------
__device__ float g_hpart[KSPL][N * F];       // 4 MB: split-K partials of x@W
__device__ float g_h[N * F];                 // 512 KB
__device__ float g_rowsum[N];
__device__ float g_opart[NT][N * F];         // 16 MB: slot = other tile index

#define ABS2MASK 0x7FFFFFFF7FFFFFFFULL

__device__ __forceinline__ u64 f2add(u64 a, u64 b) {
    u64 r; asm("add.rn.f32x2 %0, %1, %2;" : "=l"(r) : "l"(a), "l"(b)); return r;
}
__device__ __forceinline__ u64 f2fma(u64 a, u64 b, u64 c) {
    u64 r; asm("fma.rn.f32x2 %0, %1, %2, %3;" : "=l"(r) : "l"(a), "l"(b), "l"(c)); return r;
}
__device__ __forceinline__ u64 dupf(float x) {
    u64 r; unsigned u = __float_as_uint(x);
    asm("mov.b64 %0, {%1,%1};" : "=l"(r) : "r"(u)); return r;
}
__device__ __forceinline__ float unpack_sum(u64 v) {
    float lo, hi;
    asm("mov.b64 {%0,%1}, %2;" : "=f"(lo), "=f"(hi) : "l"(v));
    return lo + hi;
}
__device__ __forceinline__ void unpack2(u64 v, float& lo, float& hi) {
    asm("mov.b64 {%0,%1}, %2;" : "=f"(lo), "=f"(hi) : "l"(v));
}

#define FMA4(a, s, v) { (a).x += (s)*(v).x; (a).y += (s)*(v).y; (a).z += (s)*(v).z; (a).w += (s)*(v).w; }

// ---------------- K1: split-K GEMM partials, 4r x 4c register micro ---------
__global__ __launch_bounds__(256) void k1_gemm_part(const float* __restrict__ x,
                                                    const float* __restrict__ W) {
    __shared__ float xs[64][68];    // padded: row stride 68 kills ty conflicts
    __shared__ float ws[64][64];
    int tid = threadIdx.x;
    int r0 = blockIdx.x * 64;
    int kbase = blockIdx.y * 64;

#pragma unroll
    for (int u = 0; u < 4; u++) {
        int v = tid + u * 256;
        int r = v >> 4, c = v & 15;
        *(float4*)&xs[r][c * 4] =
            *(const float4*)&x[(size_t)(r0 + r) * FIN + kbase + c * 4];
        *(float4*)&ws[r][c * 4] =
            *(const float4*)&W[(size_t)(kbase + r) * F + c * 4];
    }
    __syncthreads();

    int tx = tid & 15, ty = tid >> 4;
    int i0 = ty * 4;
    float4 acc[4];
#pragma unroll
    for (int r = 0; r < 4; r++) acc[r] = make_float4(0.f, 0.f, 0.f, 0.f);

#pragma unroll
    for (int kk = 0; kk < 16; kk++) {
        float4 xv0 = *(const float4*)&xs[i0 + 0][kk * 4];
        float4 xv1 = *(const float4*)&xs[i0 + 1][kk * 4];
        float4 xv2 = *(const float4*)&xs[i0 + 2][kk * 4];
        float4 xv3 = *(const float4*)&xs[i0 + 3][kk * 4];
        float4 w0 = ((const float4*)&ws[kk * 4 + 0][0])[tx];
        float4 w1 = ((const float4*)&ws[kk * 4 + 1][0])[tx];
        float4 w2 = ((const float4*)&ws[kk * 4 + 2][0])[tx];
        float4 w3 = ((const float4*)&ws[kk * 4 + 3][0])[tx];
        FMA4(acc[0], xv0.x, w0); FMA4(acc[0], xv0.y, w1);
        FMA4(acc[0], xv0.z, w2); FMA4(acc[0], xv0.w, w3);
        FMA4(acc[1], xv1.x, w0); FMA4(acc[1], xv1.y, w1);
        FMA4(acc[1], xv1.z, w2); FMA4(acc[1], xv1.w, w3);
        FMA4(acc[2], xv2.x, w0); FMA4(acc[2], xv2.y, w1);
        FMA4(acc[2], xv2.z, w2); FMA4(acc[2], xv2.w, w3);
        FMA4(acc[3], xv3.x, w0); FMA4(acc[3], xv3.y, w1);
        FMA4(acc[3], xv3.z, w2); FMA4(acc[3], xv3.w, w3);
    }
#pragma unroll
    for (int r = 0; r < 4; r++)
        *(float4*)&g_hpart[blockIdx.y][(size_t)(r0 + i0 + r) * F + tx * 4] = acc[r];
}

// ---------------- K1b: g_h = sum of 8 partials; zero rowsum ----------------
__global__ __launch_bounds__(256) void k1b_reduce() {
    int idx = blockIdx.x * 256 + threadIdx.x;   // 128 x 256 = 32768 float4s
    float4 s0 = make_float4(0.f, 0.f, 0.f, 0.f);
    float4 s1 = make_float4(0.f, 0.f, 0.f, 0.f);
#pragma unroll
    for (int p = 0; p < KSPL; p += 2) {
        float4 a0 = ((const float4*)g_hpart[p + 0])[idx];
        float4 a1 = ((const float4*)g_hpart[p + 1])[idx];
        s0.x += a0.x; s0.y += a0.y; s0.z += a0.z; s0.w += a0.w;
        s1.x += a1.x; s1.y += a1.y; s1.z += a1.z; s1.w += a1.w;
    }
    float4 r;
    r.x = s0.x + s1.x; r.y = s0.y + s1.y;
    r.z = s0.z + s1.z; r.w = s0.w + s1.w;
    ((float4*)g_h)[idx] = r;
    if (idx < N) g_rowsum[idx] = 0.0f;
}

// ---------------- K23sym: R14 structure + pre-duplicated h for phase B ------
// njsdup[64][64] u64: each -h value stored as a dup'd f32x2 pair, split-pair
// layout ([2cp],[2cp+1] / [32+2cp],[32+2cp+1]) -> contiguous 256B LDS reads.
// B-loop: 3 LDS.128 + 2 f2add + 8 f2fma (NO dup MOVs). After B1, njs+Pst1
// (32KB) are dead -> hisdup restaged over them for B2.
// smem: his 16K | njs 16K | Pst1 16K | Pst2 16K | a 256B | njsdup 32K = 96.3KB
#define K23S_FLOATS (16448 + 8192)
#define K23S_SMEM (K23S_FLOATS * 4)

__global__ __launch_bounds__(256, 2) void k23_sym(const int* __restrict__ adj,
                                                  const float* __restrict__ a) {
    extern __shared__ float sm[];
    float* his    = sm;            // [64][64] rotated (i-tile h)
    float* njs    = sm + 4096;     // [64][64] rotated, negated (j-tile h)
    float* Pst1   = sm + 8192;     // [j][i] swizzled, mask adj[i,j]
    float* Pst2   = sm + 12288;    // [i][j] swizzled, mask adj[j,i]
    float* as_    = sm + 16384;    // [64]
    u64*   njsdup = (u64*)(sm + 16448);  // [64][64] u64 dup'd -h, split-pair
    u64*   hisdup = (u64*)(sm + 4096);   // overlay (njs+Pst1) after B1

    // triangular decode
    int t = blockIdx.x, ib = 0;
    while (t >= NT - ib) { t -= NT - ib; ib++; }
    int jb = ib + t;
    int gi0 = ib * 64, gj0 = jb * 64;
    bool diag = (ib == jb);

    int tid = threadIdx.x;
    int tx = tid & 15, ty = tid >> 4;
    int i0 = ty * 4, j0 = tx * 4;

    // ---- prefetch adjacency (both orientations), compress to bitmasks ----
    unsigned mij = 0, mji = 0;
#pragma unroll
    for (int k = 0; k < 4; k++) {
        int4 v = *(const int4*)&adj[(size_t)(gi0 + i0 + k) * N + gj0 + j0];
        unsigned b = (v.x > 0) | ((v.y > 0) << 1) | ((v.z > 0) << 2) | ((v.w > 0) << 3);
        mij |= b << (k * 4);
    }
    if (!diag) {
#pragma unroll
        for (int jj = 0; jj < 4; jj++) {
            int4 v = *(const int4*)&adj[(size_t)(gj0 + j0 + jj) * N + gi0 + i0];
            unsigned b = (v.x > 0) | ((v.y > 0) << 1) | ((v.z > 0) << 2) | ((v.w > 0) << 3);
            mji |= b << (jj * 4);
        }
    }

    // ---- stage his (rotated), njs (rotated+negated), njsdup, a ----
    const float4* hgi = (const float4*)(g_h + (size_t)gi0 * F);
    const float4* hgj = (const float4*)(g_h + (size_t)gj0 * F);
#pragma unroll
    for (int u = 0; u < 4; u++) {
        int v = tid + u * 256;
        int r = v >> 4, c = v & 15;
        int cp = (c + (r >> 2)) & 15;
        *(float4*)&his[r * 64 + cp * 4] = hgi[v];
        float4 nv = hgj[v];
        nv.x = -nv.x; nv.y = -nv.y; nv.z = -nv.z; nv.w = -nv.w;
        *(float4*)&njs[r * 64 + cp * 4] = nv;
        u64* nd = njsdup + r * 64;
        nd[2 * cp]          = dupf(nv.x);
        nd[2 * cp + 1]      = dupf(nv.y);
        nd[32 + 2 * cp]     = dupf(nv.z);
        nd[32 + 2 * cp + 1] = dupf(nv.w);
    }
    if (tid < 16) ((float4*)as_)[tid] = ((const float4*)a)[tid];
    __syncthreads();

    // ---- phase A: E tile, thread = 4i x 4j; hr loaded per-k ----
    u64 accA[4][4] = {};
#pragma unroll
    for (int fc = 0; fc < 16; fc++) {
        ulonglong2 av = *(const ulonglong2*)&as_[fc * 4];
        int ci = ((fc + ty) & 15) * 4;
        int cj = ((fc + tx) & 15) * 4;
        ulonglong2 nj[4];
#pragma unroll
        for (int jj = 0; jj < 4; jj++)
            nj[jj] = *(const ulonglong2*)&njs[(j0 + jj) * 64 + cj];
#pragma unroll
        for (int k = 0; k < 4; k++) {
            ulonglong2 hr = *(const ulonglong2*)&his[(i0 + k) * 64 + ci];
#pragma unroll
            for (int jj = 0; jj < 4; jj++) {
                u64 d0 = f2add(hr.x, nj[jj].x) & ABS2MASK;
                accA[k][jj] = f2fma(d0, av.x, accA[k][jj]);
                u64 d1 = f2add(hr.y, nj[jj].y) & ABS2MASK;
                accA[k][jj] = f2fma(d1, av.y, accA[k][jj]);
            }
        }
    }

    // ---- exp once, mask twice, store Pst1 / Pst2 ----
    int swzA = (tx & 7) * 4;
    int swzB = (ty & 7) * 4;
#pragma unroll
    for (int k = 0; k < 4; k++) {
        float e[4];
#pragma unroll
        for (int jj = 0; jj < 4; jj++)
            e[jj] = __expf(fmaxf(unpack_sum(accA[k][jj]), 0.f));
        int col = (i0 + k) ^ swzA;
        Pst1[(j0 + 0) * 64 + col] = (mij >> (k * 4 + 0)) & 1 ? e[0] : 0.f;
        Pst1[(j0 + 1) * 64 + col] = (mij >> (k * 4 + 1)) & 1 ? e[1] : 0.f;
        Pst1[(j0 + 2) * 64 + col] = (mij >> (k * 4 + 2)) & 1 ? e[2] : 0.f;
        Pst1[(j0 + 3) * 64 + col] = (mij >> (k * 4 + 3)) & 1 ? e[3] : 0.f;
        if (!diag) {
            float4 st;
            st.x = (mji >> (0 * 4 + k)) & 1 ? e[0] : 0.f;
            st.y = (mji >> (1 * 4 + k)) & 1 ? e[1] : 0.f;
            st.z = (mji >> (2 * 4 + k)) & 1 ? e[2] : 0.f;
            st.w = (mji >> (3 * 4 + k)) & 1 ? e[3] : 0.f;
            *(float4*)&Pst2[(i0 + k) * 64 + (j0 ^ swzB)] = st;
        }
    }
    __syncthreads();

    // ---- phase B1: O_i = sum_j P_ij * h_j (pre-dup'd -h; no MOVs) ----
    {
        u64 acc[4][2] = {};          // [f][ipair]
        u64 rsa = 0, rsb = 0;
#pragma unroll 4
        for (int jq = 0; jq < 64; jq++) {
            int swz = ((jq >> 2) & 7) * 4;
            int cfu = (((jq >> 2) + tx) & 15) * 2;
            ulonglong2 pp = *(const ulonglong2*)&Pst1[jq * 64 + (i0 ^ swz)];
            ulonglong2 hA = *(const ulonglong2*)&njsdup[jq * 64 + cfu];       // (H0,H1)
            ulonglong2 hB = *(const ulonglong2*)&njsdup[jq * 64 + 32 + cfu];  // (H2,H3)
            rsa = f2add(rsa, pp.x);
            rsb = f2add(rsb, pp.y);
            acc[0][0] = f2fma(hA.x, pp.x, acc[0][0]);
            acc[0][1] = f2fma(hA.x, pp.y, acc[0][1]);
            acc[1][0] = f2fma(hA.y, pp.x, acc[1][0]);
            acc[1][1] = f2fma(hA.y, pp.y, acc[1][1]);
            acc[2][0] = f2fma(hB.x, pp.x, acc[2][0]);
            acc[2][1] = f2fma(hB.x, pp.y, acc[2][1]);
            acc[3][0] = f2fma(hB.y, pp.x, acc[3][0]);
            acc[3][1] = f2fma(hB.y, pp.y, acc[3][1]);
        }
        if (tx == 0) {
            float s0, s1, s2, s3;
            unpack2(rsa, s0, s1); unpack2(rsb, s2, s3);
            atomicAdd(&g_rowsum[gi0 + i0 + 0], s0);
            atomicAdd(&g_rowsum[gi0 + i0 + 1], s1);
            atomicAdd(&g_rowsum[gi0 + i0 + 2], s2);
            atomicAdd(&g_rowsum[gi0 + i0 + 3], s3);
        }
        float v[4][4];
#pragma unroll
        for (int f = 0; f < 4; f++) {
            unpack2(acc[f][0], v[0][f], v[1][f]);
            unpack2(acc[f][1], v[2][f], v[3][f]);
        }
#pragma unroll
        for (int r = 0; r < 4; r++)
            *(float4*)&g_opart[jb][(size_t)(gi0 + i0 + r) * F + tx * 4] =
                make_float4(-v[r][0], -v[r][1], -v[r][2], -v[r][3]);
    }

    // ---- phase B2: O_j = sum_i P_ji * h_i (restage hisdup over njs+Pst1) ----
    if (!diag) {
        __syncthreads();             // B1 done reading Pst1/njsdup region
#pragma unroll
        for (int u = 0; u < 4; u++) {
            int v = tid + u * 256;
            int r = v >> 4, c = v & 15;
            int cp = (c + (r >> 2)) & 15;
            float4 hv4 = *(const float4*)&his[r * 64 + cp * 4];
            u64* hd = hisdup + r * 64;
            hd[2 * cp]          = dupf(hv4.x);
            hd[2 * cp + 1]      = dupf(hv4.y);
            hd[32 + 2 * cp]     = dupf(hv4.z);
            hd[32 + 2 * cp + 1] = dupf(hv4.w);
        }
        __syncthreads();

        u64 acc[4][2] = {};
        u64 rsa = 0, rsb = 0;
#pragma unroll 4
        for (int iq = 0; iq < 64; iq++) {
            int swz = ((iq >> 2) & 7) * 4;
            int cfu = (((iq >> 2) + tx) & 15) * 2;
            ulonglong2 pp = *(const ulonglong2*)&Pst2[iq * 64 + (i0 ^ swz)];
            ulonglong2 hA = *(const ulonglong2*)&hisdup[iq * 64 + cfu];
            ulonglong2 hB = *(const ulonglong2*)&hisdup[iq * 64 + 32 + cfu];
            rsa = f2add(rsa, pp.x);
            rsb = f2add(rsb, pp.y);
            acc[0][0] = f2fma(hA.x, pp.x, acc[0][0]);
            acc[0][1] = f2fma(hA.x, pp.y, acc[0][1]);
            acc[1][0] = f2fma(hA.y, pp.x, acc[1][0]);
            acc[1][1] = f2fma(hA.y, pp.y, acc[1][1]);
            acc[2][0] = f2fma(hB.x, pp.x, acc[2][0]);
            acc[2][1] = f2fma(hB.x, pp.y, acc[2][1]);
            acc[3][0] = f2fma(hB.y, pp.x, acc[3][0]);
            acc[3][1] = f2fma(hB.y, pp.y, acc[3][1]);
        }
        if (tx == 0) {
            float s0, s1, s2, s3;
            unpack2(rsa, s0, s1); unpack2(rsb, s2, s3);
            atomicAdd(&g_rowsum[gj0 + i0 + 0], s0);
            atomicAdd(&g_rowsum[gj0 + i0 + 1], s1);
            atomicAdd(&g_rowsum[gj0 + i0 + 2], s2);
            atomicAdd(&g_rowsum[gj0 + i0 + 3], s3);
        }
        float v[4][4];
#pragma unroll
        for (int f = 0; f < 4; f++) {
            unpack2(acc[f][0], v[0][f], v[1][f]);
            unpack2(acc[f][1], v[2][f], v[3][f]);
        }
#pragma unroll
        for (int r = 0; r < 4; r++)
            *(float4*)&g_opart[ib][(size_t)(gj0 + i0 + r) * F + tx * 4] =
                make_float4(v[r][0], v[r][1], v[r][2], v[r][3]);
    }
}

// ---------------- K4: out = relu((sum of 32 partials) / rowsum) ------------
__global__ __launch_bounds__(128) void k4_final(float* __restrict__ out) {
    int idx = blockIdx.x * 128 + threadIdx.x;          // 0 .. N*F-1
    float inv = 1.0f / g_rowsum[idx >> 6];
    float v[32];
#pragma unroll
    for (int p = 0; p < 32; p++) v[p] = g_opart[p][idx];
    float s0 = 0.f, s1 = 0.f, s2 = 0.f, s3 = 0.f;
#pragma unroll
    for (int p = 0; p < 32; p += 4) {
        s0 += v[p + 0]; s1 += v[p + 1]; s2 += v[p + 2]; s3 += v[p + 3];
    }
    out[idx] = fmaxf(((s0 + s1) + (s2 + s3)) * inv, 0.f);
}

// ---------------- launch ---------------------------------------------------
extern "C" void kernel_launch(void* const* d_in, const int* in_sizes, int n_in,
                              void* d_out, int out_size) {
    const float* x   = (const float*)d_in[0];
    const int*   adj = (const int*)  d_in[1];
    const float* W   = (const float*)d_in[2];
    const float* a   = (const float*)d_in[3];
    float*       out = (float*)d_out;

    cudaFuncSetAttribute(k23_sym, cudaFuncAttributeMaxDynamicSharedMemorySize, K23S_SMEM);

    dim3 g1(32, KSPL);
    k1_gemm_part<<<g1, 256>>>(x, W);
    k1b_reduce<<<128, 256>>>();
    k23_sym<<<NTRI, 256, K23S_SMEM>>>(adj, a);
    k4_final<<<N * F / 128, 128>>>(out);
}

// round 17
// speedup vs baseline: 1.1238x; 1.1238x over previous
#include <cuda_runtime.h>

#define N     2048
#define FIN   512
#define F     64
#define NT    32            // 64-row tiles per dimension
#define NTRI  528           // NT*(NT+1)/2
#define NOFF  496           // off-diagonal pairs (ib < jb)
#define KSPL  8             // k1 split-K factor

typedef unsigned long long u64;

// ---------------- scratch (static device allocations only) ----------------
__device__ float g_hpart[KSPL][N * F];       // 4 MB: split-K partials of x@W
__device__ float g_h[N * F];                 // 512 KB
__device__ float g_rowsum[N];
__device__ float g_opart[NT][N * F];         // 16 MB: slot = other tile index

#define ABS2MASK 0x7FFFFFFF7FFFFFFFULL

__device__ __forceinline__ u64 f2add(u64 a, u64 b) {
    u64 r; asm("add.rn.f32x2 %0, %1, %2;" : "=l"(r) : "l"(a), "l"(b)); return r;
}
__device__ __forceinline__ u64 f2fma(u64 a, u64 b, u64 c) {
    u64 r; asm("fma.rn.f32x2 %0, %1, %2, %3;" : "=l"(r) : "l"(a), "l"(b), "l"(c)); return r;
}
__device__ __forceinline__ u64 dupf(float x) {
    u64 r; unsigned u = __float_as_uint(x);
    asm("mov.b64 %0, {%1,%1};" : "=l"(r) : "r"(u)); return r;
}
__device__ __forceinline__ float unpack_sum(u64 v) {
    float lo, hi;
    asm("mov.b64 {%0,%1}, %2;" : "=f"(lo), "=f"(hi) : "l"(v));
    return lo + hi;
}
__device__ __forceinline__ void unpack2(u64 v, float& lo, float& hi) {
    asm("mov.b64 {%0,%1}, %2;" : "=f"(lo), "=f"(hi) : "l"(v));
}

#define FMA4(a, s, v) { (a).x += (s)*(v).x; (a).y += (s)*(v).y; (a).z += (s)*(v).z; (a).w += (s)*(v).w; }

// ---------------- K1: split-K GEMM partials, 4r x 4c register micro ---------
__global__ __launch_bounds__(256) void k1_gemm_part(const float* __restrict__ x,
                                                    const float* __restrict__ W) {
    __shared__ float xs[64][68];    // padded: row stride 68 kills ty conflicts
    __shared__ float ws[64][64];
    int tid = threadIdx.x;
    int r0 = blockIdx.x * 64;
    int kbase = blockIdx.y * 64;

#pragma unroll
    for (int u = 0; u < 4; u++) {
        int v = tid + u * 256;
        int r = v >> 4, c = v & 15;
        *(float4*)&xs[r][c * 4] =
            *(const float4*)&x[(size_t)(r0 + r) * FIN + kbase + c * 4];
        *(float4*)&ws[r][c * 4] =
            *(const float4*)&W[(size_t)(kbase + r) * F + c * 4];
    }
    __syncthreads();

    int tx = tid & 15, ty = tid >> 4;
    int i0 = ty * 4;
    float4 acc[4];
#pragma unroll
    for (int r = 0; r < 4; r++) acc[r] = make_float4(0.f, 0.f, 0.f, 0.f);

#pragma unroll
    for (int kk = 0; kk < 16; kk++) {
        float4 xv0 = *(const float4*)&xs[i0 + 0][kk * 4];
        float4 xv1 = *(const float4*)&xs[i0 + 1][kk * 4];
        float4 xv2 = *(const float4*)&xs[i0 + 2][kk * 4];
        float4 xv3 = *(const float4*)&xs[i0 + 3][kk * 4];
        float4 w0 = ((const float4*)&ws[kk * 4 + 0][0])[tx];
        float4 w1 = ((const float4*)&ws[kk * 4 + 1][0])[tx];
        float4 w2 = ((const float4*)&ws[kk * 4 + 2][0])[tx];
        float4 w3 = ((const float4*)&ws[kk * 4 + 3][0])[tx];
        FMA4(acc[0], xv0.x, w0); FMA4(acc[0], xv0.y, w1);
        FMA4(acc[0], xv0.z, w2); FMA4(acc[0], xv0.w, w3);
        FMA4(acc[1], xv1.x, w0); FMA4(acc[1], xv1.y, w1);
        FMA4(acc[1], xv1.z, w2); FMA4(acc[1], xv1.w, w3);
        FMA4(acc[2], xv2.x, w0); FMA4(acc[2], xv2.y, w1);
        FMA4(acc[2], xv2.z, w2); FMA4(acc[2], xv2.w, w3);
        FMA4(acc[3], xv3.x, w0); FMA4(acc[3], xv3.y, w1);
        FMA4(acc[3], xv3.z, w2); FMA4(acc[3], xv3.w, w3);
    }
#pragma unroll
    for (int r = 0; r < 4; r++)
        *(float4*)&g_hpart[blockIdx.y][(size_t)(r0 + i0 + r) * F + tx * 4] = acc[r];
}

// ---------------- K1b: g_h = sum of 8 partials; zero rowsum ----------------
__global__ __launch_bounds__(256) void k1b_reduce() {
    int idx = blockIdx.x * 256 + threadIdx.x;   // 128 x 256 = 32768 float4s
    float4 s0 = make_float4(0.f, 0.f, 0.f, 0.f);
    float4 s1 = make_float4(0.f, 0.f, 0.f, 0.f);
#pragma unroll
    for (int p = 0; p < KSPL; p += 2) {
        float4 a0 = ((const float4*)g_hpart[p + 0])[idx];
        float4 a1 = ((const float4*)g_hpart[p + 1])[idx];
        s0.x += a0.x; s0.y += a0.y; s0.z += a0.z; s0.w += a0.w;
        s1.x += a1.x; s1.y += a1.y; s1.z += a1.z; s1.w += a1.w;
    }
    float4 r;
    r.x = s0.x + s1.x; r.y = s0.y + s1.y;
    r.z = s0.z + s1.z; r.w = s0.w + s1.w;
    ((float4*)g_h)[idx] = r;
    if (idx < N) g_rowsum[idx] = 0.0f;
}

// ---------------- K23sym: R14 hot loops; diag tiles scheduled LAST ----------
// bid 0..495 -> off-diagonal pairs (ib < jb); bid 496..527 -> diagonal tiles.
// Diag tiles do ~55% of the work (no Pst2 store / B2 loop); placing them in
// the final wave shortens the straggler tail (1.78 waves at 296 slots).
#define K23S_SMEM ((4096 * 4 + 64) * 4)   // his, njs, Pst1, Pst2, a = 64.3KB

__global__ __launch_bounds__(256, 2) void k23_sym(const int* __restrict__ adj,
                                                  const float* __restrict__ a) {
    extern __shared__ float sm[];
    float* his  = sm;            // [64][64] rotated (i-tile h)
    float* njs  = sm + 4096;     // [64][64] rotated, negated (j-tile h)
    float* Pst1 = sm + 8192;     // [j][i] swizzled, mask adj[i,j]
    float* Pst2 = sm + 12288;    // [i][j] swizzled, mask adj[j,i]
    float* as_  = sm + 16384;    // [64]

    // decode: off-diag pairs first, diagonal tiles last
    int ib, jb;
    if (blockIdx.x < NOFF) {
        int t = blockIdx.x;
        ib = 0;
        while (t >= NT - 1 - ib) { t -= NT - 1 - ib; ib++; }
        jb = ib + 1 + t;
    } else {
        ib = jb = blockIdx.x - NOFF;
    }
    int gi0 = ib * 64, gj0 = jb * 64;
    bool diag = (ib == jb);

    int tid = threadIdx.x;
    int tx = tid & 15, ty = tid >> 4;
    int i0 = ty * 4, j0 = tx * 4;

    // ---- prefetch adjacency (both orientations), compress to bitmasks ----
    unsigned mij = 0, mji = 0;
#pragma unroll
    for (int k = 0; k < 4; k++) {
        int4 v = *(const int4*)&adj[(size_t)(gi0 + i0 + k) * N + gj0 + j0];
        unsigned b = (v.x > 0) | ((v.y > 0) << 1) | ((v.z > 0) << 2) | ((v.w > 0) << 3);
        mij |= b << (k * 4);
    }
    if (!diag) {
#pragma unroll
        for (int jj = 0; jj < 4; jj++) {
            int4 v = *(const int4*)&adj[(size_t)(gj0 + j0 + jj) * N + gi0 + i0];
            unsigned b = (v.x > 0) | ((v.y > 0) << 1) | ((v.z > 0) << 2) | ((v.w > 0) << 3);
            mji |= b << (jj * 4);
        }
    }

    // ---- stage his (rotated), njs (rotated + negated), a ----
    const float4* hgi = (const float4*)(g_h + (size_t)gi0 * F);
    const float4* hgj = (const float4*)(g_h + (size_t)gj0 * F);
#pragma unroll
    for (int u = 0; u < 4; u++) {
        int v = tid + u * 256;
        int r = v >> 4, c = v & 15;
        int cp = (c + (r >> 2)) & 15;
        *(float4*)&his[r * 64 + cp * 4] = hgi[v];
        float4 nv = hgj[v];
        nv.x = -nv.x; nv.y = -nv.y; nv.z = -nv.z; nv.w = -nv.w;
        *(float4*)&njs[r * 64 + cp * 4] = nv;
    }
    if (tid < 16) ((float4*)as_)[tid] = ((const float4*)a)[tid];
    __syncthreads();

    // ---- phase A: E tile, thread = 4i x 4j; hr loaded per-k ----
    u64 accA[4][4] = {};
#pragma unroll
    for (int fc = 0; fc < 16; fc++) {
        ulonglong2 av = *(const ulonglong2*)&as_[fc * 4];
        int ci = ((fc + ty) & 15) * 4;
        int cj = ((fc + tx) & 15) * 4;
        ulonglong2 nj[4];
#pragma unroll
        for (int jj = 0; jj < 4; jj++)
            nj[jj] = *(const ulonglong2*)&njs[(j0 + jj) * 64 + cj];
#pragma unroll
        for (int k = 0; k < 4; k++) {
            ulonglong2 hr = *(const ulonglong2*)&his[(i0 + k) * 64 + ci];
#pragma unroll
            for (int jj = 0; jj < 4; jj++) {
                u64 d0 = f2add(hr.x, nj[jj].x) & ABS2MASK;
                accA[k][jj] = f2fma(d0, av.x, accA[k][jj]);
                u64 d1 = f2add(hr.y, nj[jj].y) & ABS2MASK;
                accA[k][jj] = f2fma(d1, av.y, accA[k][jj]);
            }
        }
    }

    // ---- exp once, mask twice, store Pst1 / Pst2 ----
    int swzA = (tx & 7) * 4;
    int swzB = (ty & 7) * 4;
#pragma unroll
    for (int k = 0; k < 4; k++) {
        float e[4];
#pragma unroll
        for (int jj = 0; jj < 4; jj++)
            e[jj] = __expf(fmaxf(unpack_sum(accA[k][jj]), 0.f));
        int col = (i0 + k) ^ swzA;
        Pst1[(j0 + 0) * 64 + col] = (mij >> (k * 4 + 0)) & 1 ? e[0] : 0.f;
        Pst1[(j0 + 1) * 64 + col] = (mij >> (k * 4 + 1)) & 1 ? e[1] : 0.f;
        Pst1[(j0 + 2) * 64 + col] = (mij >> (k * 4 + 2)) & 1 ? e[2] : 0.f;
        Pst1[(j0 + 3) * 64 + col] = (mij >> (k * 4 + 3)) & 1 ? e[3] : 0.f;
        if (!diag) {
            float4 st;
            st.x = (mji >> (0 * 4 + k)) & 1 ? e[0] : 0.f;
            st.y = (mji >> (1 * 4 + k)) & 1 ? e[1] : 0.f;
            st.z = (mji >> (2 * 4 + k)) & 1 ? e[2] : 0.f;
            st.w = (mji >> (3 * 4 + k)) & 1 ? e[3] : 0.f;
            *(float4*)&Pst2[(i0 + k) * 64 + (j0 ^ swzB)] = st;
        }
    }
    __syncthreads();

    // ---- phase B1: O_i = sum_j P_ij * h_j (acc[f][i-pair]) ----
    {
        u64 acc[4][2] = {};
        u64 rsa = 0, rsb = 0;
#pragma unroll 4
        for (int jq = 0; jq < 64; jq++) {
            int swz = ((jq >> 2) & 7) * 4;
            int cf = (((jq >> 2) + tx) & 15) * 4;
            ulonglong2 pp = *(const ulonglong2*)&Pst1[jq * 64 + (i0 ^ swz)];
            ulonglong2 hv = *(const ulonglong2*)&njs[jq * 64 + cf];
            rsa = f2add(rsa, pp.x);
            rsb = f2add(rsb, pp.y);
            float h0, h1, h2, h3;
            unpack2(hv.x, h0, h1); unpack2(hv.y, h2, h3);
            u64 H0 = dupf(h0), H1 = dupf(h1), H2 = dupf(h2), H3 = dupf(h3);
            acc[0][0] = f2fma(H0, pp.x, acc[0][0]);
            acc[0][1] = f2fma(H0, pp.y, acc[0][1]);
            acc[1][0] = f2fma(H1, pp.x, acc[1][0]);
            acc[1][1] = f2fma(H1, pp.y, acc[1][1]);
            acc[2][0] = f2fma(H2, pp.x, acc[2][0]);
            acc[2][1] = f2fma(H2, pp.y, acc[2][1]);
            acc[3][0] = f2fma(H3, pp.x, acc[3][0]);
            acc[3][1] = f2fma(H3, pp.y, acc[3][1]);
        }
        if (tx == 0) {
            float s0, s1, s2, s3;
            unpack2(rsa, s0, s1); unpack2(rsb, s2, s3);
            atomicAdd(&g_rowsum[gi0 + i0 + 0], s0);
            atomicAdd(&g_rowsum[gi0 + i0 + 1], s1);
            atomicAdd(&g_rowsum[gi0 + i0 + 2], s2);
            atomicAdd(&g_rowsum[gi0 + i0 + 3], s3);
        }
        float v[4][4];
#pragma unroll
        for (int f = 0; f < 4; f++) {
            unpack2(acc[f][0], v[0][f], v[1][f]);
            unpack2(acc[f][1], v[2][f], v[3][f]);
        }
#pragma unroll
        for (int r = 0; r < 4; r++)
            *(float4*)&g_opart[jb][(size_t)(gi0 + i0 + r) * F + tx * 4] =
                make_float4(-v[r][0], -v[r][1], -v[r][2], -v[r][3]);
    }

    // ---- phase B2: O_j = sum_i P_ji * h_i ----
    if (!diag) {
        u64 acc[4][2] = {};
        u64 rsa = 0, rsb = 0;
#pragma unroll 4
        for (int iq = 0; iq < 64; iq++) {
            int swz = ((iq >> 2) & 7) * 4;
            int cf = (((iq >> 2) + tx) & 15) * 4;
            ulonglong2 pp = *(const ulonglong2*)&Pst2[iq * 64 + (i0 ^ swz)];
            ulonglong2 hv = *(const ulonglong2*)&his[iq * 64 + cf];
            rsa = f2add(rsa, pp.x);
            rsb = f2add(rsb, pp.y);
            float h0, h1, h2, h3;
            unpack2(hv.x, h0, h1); unpack2(hv.y, h2, h3);
            u64 H0 = dupf(h0), H1 = dupf(h1), H2 = dupf(h2), H3 = dupf(h3);
            acc[0][0] = f2fma(H0, pp.x, acc[0][0]);
            acc[0][1] = f2fma(H0, pp.y, acc[0][1]);
            acc[1][0] = f2fma(H1, pp.x, acc[1][0]);
            acc[1][1] = f2fma(H1, pp.y, acc[1][1]);
            acc[2][0] = f2fma(H2, pp.x, acc[2][0]);
            acc[2][1] = f2fma(H2, pp.y, acc[2][1]);
            acc[3][0] = f2fma(H3, pp.x, acc[3][0]);
            acc[3][1] = f2fma(H3, pp.y, acc[3][1]);
        }
        if (tx == 0) {
            float s0, s1, s2, s3;
            unpack2(rsa, s0, s1); unpack2(rsb, s2, s3);
            atomicAdd(&g_rowsum[gj0 + i0 + 0], s0);
            atomicAdd(&g_rowsum[gj0 + i0 + 1], s1);
            atomicAdd(&g_rowsum[gj0 + i0 + 2], s2);
            atomicAdd(&g_rowsum[gj0 + i0 + 3], s3);
        }
        float v[4][4];
#pragma unroll
        for (int f = 0; f < 4; f++) {
            unpack2(acc[f][0], v[0][f], v[1][f]);
            unpack2(acc[f][1], v[2][f], v[3][f]);
        }
#pragma unroll
        for (int r = 0; r < 4; r++)
            *(float4*)&g_opart[ib][(size_t)(gj0 + i0 + r) * F + tx * 4] =
                make_float4(v[r][0], v[r][1], v[r][2], v[r][3]);
    }
}

// ---------------- K4: out = relu((sum of 32 partials) / rowsum) ------------
__global__ __launch_bounds__(128) void k4_final(float* __restrict__ out) {
    int idx = blockIdx.x * 128 + threadIdx.x;          // 0 .. N*F-1
    float inv = 1.0f / g_rowsum[idx >> 6];
    float v[32];
#pragma unroll
    for (int p = 0; p < 32; p++) v[p] = g_opart[p][idx];
    float s0 = 0.f, s1 = 0.f, s2 = 0.f, s3 = 0.f;
#pragma unroll
    for (int p = 0; p < 32; p += 4) {
        s0 += v[p + 0]; s1 += v[p + 1]; s2 += v[p + 2]; s3 += v[p + 3];
    }
    out[idx] = fmaxf(((s0 + s1) + (s2 + s3)) * inv, 0.f);
}

// ---------------- launch ---------------------------------------------------
extern "C" void kernel_launch(void* const* d_in, const int* in_sizes, int n_in,
                              void* d_out, int out_size) {
    const float* x   = (const float*)d_in[0];
    const int*   adj = (const int*)  d_in[1];
    const float* W   = (const float*)d_in[2];
    const float* a   = (const float*)d_in[3];
    float*       out = (float*)d_out;

    cudaFuncSetAttribute(k23_sym, cudaFuncAttributeMaxDynamicSharedMemorySize, K23S_SMEM);

    dim3 g1(32, KSPL);
    k1_gemm_part<<<g1, 256>>>(x, W);
    k1b_reduce<<<128, 256>>>();
    k23_sym<<<NTRI, 256, K23S_SMEM>>>(adj, a);
    k4_final<<<N * F / 128, 128>>>(out);
}